// round 10
// baseline (speedup 1.0000x reference)
#include <cuda_runtime.h>
#include <cuda_bf16.h>

// SSIM loss: inputs (16,3,512,512) fp32 x2, output scalar fp32.
// Separable 11-tap Gaussian; 4 conv fields {a, b, (a+b)^2, (a-b)^2}:
//   sigma1+sigma2 = (Ep+Em)/2 - mu1^2 - mu2^2,  sigma12 = (Ep-Em)/4 - mu1*mu2.
//
// R9: TX=54/TY=32, phase-A strips of 8 rows -> 64 halo cols x 4 strips = 256
// items = full thread utilization; 32-reg accumulators -> 3 blocks/SM;
// in-kernel last-block finalization (no second kernel on the critical path).

#define W_IMG 512
#define H_IMG 512
#define PLANE (512 * 512)
#define TX 54
#define TY 32
#define HC 64                      // halo cols (covers TX+10, padded to 64)
#define SVS 65                     // smem row stride (odd -> conflict-free)
#define GX 10                      // 10 tiles x 54 = 540 cols (>=512, masked)
#define GY 16
#define N_BLOCKS (GX * GY * 48)    // 7680
#define N_PIX 12582912.0

__device__ float g_part[N_BLOCKS];
__device__ unsigned int g_count;   // static-init 0; self-resetting

// Gaussian window, sigma=1.5, ws=11, normalized. Function-local, constant
// indices after unroll -> FFMA with immediate multiplier (rt_SMSP=1).
#define DECL_GW()                                                        \
    const float GW[11] = {                                               \
        0.00102838f, 0.00759876f, 0.03600077f, 0.10936069f, 0.21300554f, \
        0.26601173f,                                                     \
        0.21300554f, 0.10936069f, 0.03600077f, 0.00759876f, 0.00102838f }

__device__ __forceinline__ float clip01(float v) {
    return fminf(fmaxf(v, 0.0f), 1.0f);   // fmaxf(NaN,0)=0 handles nan_to_num
}

extern __shared__ float smem_raw[];
// layout: sV[4][TY][SVS] | pad[8] | red[8]

__global__ __launch_bounds__(256, 3)
void ssim_main_kernel(const float* __restrict__ img1,
                      const float* __restrict__ img2,
                      float* __restrict__ out) {
    DECL_GW();
    float* sV0 = smem_raw;                 // vertically filtered: a
    float* sV1 = sV0 + TY * SVS;           // b
    float* sV2 = sV1 + TY * SVS;           // (a+b)^2
    float* sV3 = sV2 + TY * SVS;           // (a-b)^2
    float* red = sV3 + TY * SVS + 8;       // 8 floats (after overflow pad)
    __shared__ unsigned int s_is_last;
    __shared__ double dred[8];

    const int tid   = threadIdx.x;
    const int plane = blockIdx.z;
    const int cx0   = blockIdx.x * TX;
    const int cy0   = blockIdx.y * TY;
    const float* __restrict__ A = img1 + (size_t)plane * PLANE;
    const float* __restrict__ B = img2 + (size_t)plane * PLANE;

    // ---------------- Phase A: vertical 11-tap conv ----------------
    // 64 halo cols x 4 strips of 8 output rows = 256 items (all threads).
    {
        const int col   = tid & 63;        // 0..63
        const int strip = tid >> 6;        // 0..3
        const int r0    = strip * 8;
        const int gc    = cx0 + col - 5;
        const bool okc  = ((unsigned)gc < (unsigned)W_IMG);

        float acc0[8], acc1[8], acc2[8], acc3[8];
        #pragma unroll
        for (int r = 0; r < 8; r++) {
            acc0[r] = 0.0f; acc1[r] = 0.0f; acc2[r] = 0.0f; acc3[r] = 0.0f;
        }

        #pragma unroll
        for (int q = 0; q < 18; q++) {
            const int gr = cy0 + r0 + q - 5;
            float a = 0.0f, b = 0.0f;
            if (okc && (unsigned)gr < (unsigned)H_IMG) {
                const int idx = gr * W_IMG + gc;
                a = A[idx];
                b = B[idx];
            }
            a = clip01(a);
            b = clip01(b);
            const float s = a + b, d = a - b;
            const float p = s * s, m = d * d;
            #pragma unroll
            for (int rr = (q > 10 ? q - 10 : 0); rr <= (q < 7 ? q : 7); rr++) {
                const float w = GW[q - rr];          // immediate
                acc0[rr] = fmaf(a, w, acc0[rr]);
                acc1[rr] = fmaf(b, w, acc1[rr]);
                acc2[rr] = fmaf(p, w, acc2[rr]);
                acc3[rr] = fmaf(m, w, acc3[rr]);
            }
        }
        #pragma unroll
        for (int rr = 0; rr < 8; rr++) {
            const int o = (r0 + rr) * SVS + col;
            sV0[o] = acc0[rr];
            sV1[o] = acc1[rr];
            sV2[o] = acc2[rr];
            sV3[o] = acc3[rr];
        }
    }
    __syncthreads();

    // ---------------- Phase B: horizontal conv + SSIM ----------------
    // warp = 32 rows of one 7-col group; stride 65 -> bank = lane + c, CF.
    const int orow = tid & 31;        // 0..31
    const int grp  = tid >> 5;        // 0..7 (cols grp*7 .. grp*7+6)
    const int base = orow * SVS + grp * 7;

    float acc0[7], acc1[7], acc2[7], acc3[7];
    #pragma unroll
    for (int o = 0; o < 7; o++) {
        acc0[o] = 0.0f; acc1[o] = 0.0f; acc2[o] = 0.0f; acc3[o] = 0.0f;
    }

    #pragma unroll
    for (int p = 0; p < 17; p++) {
        const float v0 = sV0[base + p];
        const float v1 = sV1[base + p];
        const float v2 = sV2[base + p];
        const float v3 = sV3[base + p];
        #pragma unroll
        for (int o = (p > 10 ? p - 10 : 0); o <= (p < 6 ? p : 6); o++) {
            const float w = GW[p - o];
            acc0[o] = fmaf(v0, w, acc0[o]);
            acc1[o] = fmaf(v1, w, acc1[o]);
            acc2[o] = fmaf(v2, w, acc2[o]);
            acc3[o] = fmaf(v3, w, acc3[o]);
        }
    }

    const float C1 = 0.000101f;   // 0.01^2 + 1e-6
    const float C2 = 0.000901f;   // 0.03^2 + 1e-6
    float lsum = 0.0f;
    #pragma unroll
    for (int o = 0; o < 7; o++) {
        const int lc = grp * 7 + o;                      // tile-local col
        const bool valid = (lc < TX) && ((cx0 + lc) < W_IMG);
        const float mu1 = acc0[o], mu2 = acc1[o];
        const float Ep = acc2[o], Em = acc3[o];
        const float mu1s = mu1 * mu1;
        const float mu2s = mu2 * mu2;
        const float mu12 = mu1 * mu2;
        const float musum = mu1s + mu2s;
        const float ssum = fmaf(0.5f, Ep + Em, -musum);  // sigma1+sigma2
        const float s12  = fmaf(0.25f, Ep - Em, -mu12);  // sigma12
        const float num = fmaf(2.0f, mu12, C1) * fmaf(2.0f, s12, C2);
        const float den = (musum + C1) * (ssum + C2);
        if (valid) lsum += __fdividef(num, den);
    }

    // ---------------- Block reduction -> partial sum ----------------
    #pragma unroll
    for (int off = 16; off > 0; off >>= 1)
        lsum += __shfl_xor_sync(0xffffffffu, lsum, off);

    const int warp = tid >> 5;
    const int lane = tid & 31;
    if (lane == 0) red[warp] = lsum;
    __syncthreads();

    const int bid = (blockIdx.z * GY + blockIdx.y) * GX + blockIdx.x;
    if (tid == 0) {
        float v = 0.0f;
        #pragma unroll
        for (int i = 0; i < 8; i++) v += red[i];
        g_part[bid] = v;
        __threadfence();
        const unsigned int c = atomicAdd(&g_count, 1u);
        s_is_last = (c == (unsigned)(N_BLOCKS - 1)) ? 1u : 0u;
    }
    __syncthreads();

    // ---------------- Last block: final reduction ----------------
    if (s_is_last) {
        double s = 0.0;
        for (int i = tid; i < N_BLOCKS; i += 256) s += (double)g_part[i];
        #pragma unroll
        for (int off = 16; off > 0; off >>= 1)
            s += __shfl_xor_sync(0xffffffffu, s, off);
        if (lane == 0) dred[warp] = s;
        __syncthreads();
        if (warp == 0) {
            double v = (lane < 8) ? dred[lane] : 0.0;
            #pragma unroll
            for (int off = 4; off > 0; off >>= 1)
                v += __shfl_xor_sync(0xffffffffu, v, off);
            if (lane == 0) {
                out[0] = (float)(1.0 - v / N_PIX);
                g_count = 0;                 // reset for next launch
            }
        }
    }
}

extern "C" void kernel_launch(void* const* d_in, const int* in_sizes, int n_in,
                              void* d_out, int out_size) {
    const float* img1 = (const float*)d_in[0];
    const float* img2 = (const float*)d_in[1];
    float* out = (float*)d_out;

    const int smem_bytes = (4 * TY * SVS + 8 + 8) * 4;   // ~33.3 KB
    cudaFuncSetAttribute(ssim_main_kernel,
                         cudaFuncAttributeMaxDynamicSharedMemorySize,
                         smem_bytes);

    dim3 grid(GX, GY, 48);   // 10 x 16 x 48 = 7680 blocks
    ssim_main_kernel<<<grid, 256, smem_bytes>>>(img1, img2, out);
}